// round 16
// baseline (speedup 1.0000x reference)
#include <cuda_runtime.h>

// inputs (128, 64, 64, 32) fp32 => B=128, N=64 rows/batch, D=2048.
// loss = mean_b( || sum_n att[b,n,:] ||^2 - sum_n <att_n,att_n> ),
// att = x / max(||x||,1e-12) row-wise.
//
// TRUE SINGLE-READ design (grid 128 x 1024 thr, one CTA per batch):
// warp (rA,qq) covers quarter-row; thread holds v[4] of row s*8+rA and
// accumulates acc[4] for its 4 fixed columns. The same registers feed the
// row sumsq AND the weighted column sum -> x is read exactly once.
// One barrier per 8-row subtile (double-buffered wsA).

#define BB   128
#define NN   64
#define DD   2048
#define NF4  (DD / 4)      // 512 f4 columns
#define NT   1024
#define ST   8             // subtiles per batch
#define SR   8             // rows per subtile

__device__ double       g_part[BB];
__device__ unsigned int g_done;      // monotonic (never reset)

__global__ __launch_bounds__(NT) void fused_loss(const float* __restrict__ x,
                                                 float* __restrict__ out) {
    __shared__ float  wsA[2][SR][4];     // double-buffered row quarter-sumsq
    __shared__ float4 spad[SR][129];     // rA-combine pad (129: bank rotate)
    __shared__ float  w1[NT / 32], w2[NT / 32];
    __shared__ bool   s_last;
    __shared__ double sdd[BB];

    const int b    = blockIdx.x;
    const int t    = threadIdx.x;
    const int warp = t >> 5;
    const int lane = t & 31;
    const int rA   = warp >> 2;          // row within subtile (0..7)
    const int qq   = warp & 3;           // quarter of the row (0..3)
    const float4* base4 = reinterpret_cast<const float4*>(x + (size_t)b * NN * DD);

    float4 acc[4];
    #pragma unroll
    for (int j = 0; j < 4; j++) acc[j] = make_float4(0.f, 0.f, 0.f, 0.f);
    float diag = 0.f;                    // only (qq==0, lane==0) threads

    #pragma unroll 1
    for (int s = 0; s < ST; s++) {
        const float4* p = base4 + (size_t)(s * SR + rA) * NF4 + qq * 128 + lane;

        // load this thread's 4 f4 of the row (read ONCE)
        float4 v[4];
        #pragma unroll
        for (int j = 0; j < 4; j++) v[j] = p[j * 32];

        // quarter-row sum of squares
        float c0 = v[0].x*v[0].x + v[0].y*v[0].y + v[0].z*v[0].z + v[0].w*v[0].w;
        float c1 = v[1].x*v[1].x + v[1].y*v[1].y + v[1].z*v[1].z + v[1].w*v[1].w;
        float c2 = v[2].x*v[2].x + v[2].y*v[2].y + v[2].z*v[2].z + v[2].w*v[2].w;
        float c3 = v[3].x*v[3].x + v[3].y*v[3].y + v[3].z*v[3].z + v[3].w*v[3].w;
        float ss = (c0 + c1) + (c2 + c3);
        #pragma unroll
        for (int o = 16; o; o >>= 1) ss += __shfl_xor_sync(0xffffffffu, ss, o);
        if (lane == 0) wsA[s & 1][rA][qq] = ss;
        __syncthreads();                 // one barrier per subtile

        // full row sumsq -> inv (uniform per warp; broadcast LDS)
        const float* wq = wsA[s & 1][rA];
        const float rs  = (wq[0] + wq[1]) + (wq[2] + wq[3]);
        const float inv = rsqrtf(fmaxf(rs, 1e-24f));   // 1/max(||row||,1e-12)
        if (qq == 0 && lane == 0) diag += rs * inv * inv;

        // weighted column accumulation from the SAME registers (no re-read)
        #pragma unroll
        for (int j = 0; j < 4; j++) {
            acc[j].x = fmaf(inv, v[j].x, acc[j].x);
            acc[j].y = fmaf(inv, v[j].y, acc[j].y);
            acc[j].z = fmaf(inv, v[j].z, acc[j].z);
            acc[j].w = fmaf(inv, v[j].w, acc[j].w);
        }
        // next subtile writes wsA[(s+1)&1]: no race with slow readers of this one
    }

    // ---------------- combine acc over the 8 rA groups ----------------------
    // For each j: thread t holds col qq*128 + j*32 + lane of rA's partial.
    // spad[rA][qq*32+lane]; threads t<128 sum the 8 rA entries and square.
    float v1 = 0.f;
    #pragma unroll 1
    for (int j = 0; j < 4; j++) {
        __syncthreads();                 // previous round's reads done
        spad[rA][qq * 32 + lane] = acc[j];
        __syncthreads();
        if (t < 128) {
            float sx = 0.f, sy = 0.f, sz = 0.f, sw = 0.f;
            #pragma unroll
            for (int r = 0; r < SR; r++) {
                const float4 q = spad[r][t];
                sx += q.x; sy += q.y; sz += q.z; sw += q.w;
            }
            v1 += sx * sx + sy * sy + sz * sz + sw * sw;
        }
    }

    // reduce v1 (threads t<128) and diag (8 scattered lane0 threads)
    float v2 = diag;
    #pragma unroll
    for (int o = 16; o; o >>= 1) {
        v1 += __shfl_xor_sync(0xffffffffu, v1, o);
        v2 += __shfl_xor_sync(0xffffffffu, v2, o);
    }
    if (lane == 0) { w1[warp] = v1; w2[warp] = v2; }
    __syncthreads();

    if (t == 0) {
        float t1 = 0.f, t2 = 0.f;
        #pragma unroll
        for (int i = 0; i < NT / 32; i++) { t1 += w1[i]; t2 += w2[i]; }
        g_part[b] = (double)t1 - (double)t2;
        __threadfence();
        unsigned int old = atomicAdd(&g_done, 1u);
        s_last = ((old & (unsigned int)(BB - 1)) == (unsigned int)(BB - 1));
    }
    __syncthreads();
    if (!s_last) return;

    // ---------------- finisher: combine 128 per-batch doubles ---------------
    __threadfence();
    if (t < BB) sdd[t] = g_part[t];
    __syncthreads();
    #pragma unroll
    for (int o = BB / 2; o; o >>= 1) {
        if (t < o) sdd[t] += sdd[t + o];
        __syncthreads();
    }
    if (t == 0) out[0] = (float)(sdd[0] / (double)BB);
}

extern "C" void kernel_launch(void* const* d_in, const int* in_sizes, int n_in,
                              void* d_out, int out_size) {
    (void)in_sizes; (void)n_in; (void)out_size;
    const float* x = (const float*)d_in[0];
    float* out = (float*)d_out;
    fused_loss<<<BB, NT>>>(x, out);
}